// round 12
// baseline (speedup 1.0000x reference)
#include <cuda_runtime.h>
#include <math.h>

#define BB 8
#define NN 4096
#define DD 1024
#define HH 1792

#define GRID 296          // 148 SMs x 2 CTAs (forced by launch_bounds)
#define TPB 256
#define BPB 37            // blocks per batch in phases A and D (296/8)
#define NCHU 256          // h-chunks in phase B
#define HPERU 7           // 256 * 7 = 1792
#define CGRP 8            // partials per phase-C block
#define NSAVE 25          // rows of x retained in smem per block (100 KB)
#define SMEM_DYN (NSAVE * DD * 4)

// Scratch (allocation-free contract): __device__ globals.
__device__ float g_xbar[BB * DD];          // mean_n x  (atomic-accumulated)
__device__ float g_upart[NCHU][BB * DD];   // partial Wq^T @ kbar
__device__ float g_u[BB * DD];             // reduced u (atomic-accumulated)
__device__ float g_c[BB];                  // bq . kbar (atomic-accumulated)
__device__ unsigned g_bar;                 // grid barrier counter

// ---------------------------------------------------------------------------
// K0: reset accumulators + barrier counter (runs before k_main each replay).
__global__ void k_zero() {
    int i = blockIdx.x * blockDim.x + threadIdx.x;
    if (i < BB * DD) { g_xbar[i] = 0.f; g_u[i] = 0.f; }
    if (i < BB) g_c[i] = 0.f;
    if (i == 0) g_bar = 0u;
}

// ---------------------------------------------------------------------------
// Software grid barrier. Safe: all GRID blocks co-resident
// (512 thr/SM x 128 regs = full RF; smem 2 x 100.2 KB <= 228 KB).
__device__ __forceinline__ void gridbar(unsigned target) {
    __syncthreads();
    if (threadIdx.x == 0) {
        __threadfence();
        atomicAdd(&g_bar, 1u);
        unsigned v;
        do {
            asm volatile("ld.volatile.global.u32 %0, [%1];"
                         : "=r"(v) : "l"(&g_bar));
            if (v < target) __nanosleep(64);
        } while (v < target);
        __threadfence();
    }
    __syncthreads();
}

// ---------------------------------------------------------------------------
__global__ void __launch_bounds__(TPB, 2)
k_main(const float* __restrict__ x,  const float* __restrict__ Wq,
       const float* __restrict__ bq, const float* __restrict__ Wk,
       const float* __restrict__ bk, float* __restrict__ out) {
    const int t = threadIdx.x;
    const int blk = blockIdx.x;
    const int warp = t >> 5, lane = t & 31;
    __shared__ float s_kb[HPERU][BB];
    extern __shared__ float4 s_x[];            // [NSAVE][DD/4]

    // Block's row range (same in phases A and D).
    const int myb = blk / BPB;                 // 0..7
    const int myc = blk % BPB;
    const int n0 = (myc * NN) / BPB;
    const int n1 = ((myc + 1) * NN) / BPB;

    // ===== Phase A: xbar += x rows; first NSAVE rows retained in smem =====
    {
        const float4* xp = (const float4*)(x + (size_t)myb * NN * DD);

        float4 acc = make_float4(0.f, 0.f, 0.f, 0.f);
        // rows kept in smem
        #pragma unroll 5
        for (int j = 0; j < NSAVE; j++) {
            float4 v = xp[(size_t)(n0 + j) * (DD / 4) + t];
            acc.x += v.x; acc.y += v.y; acc.z += v.z; acc.w += v.w;
            s_x[j * (DD / 4) + t] = v;
        }
        // remaining rows, unroll 8
        int n = n0 + NSAVE;
        for (; n + 8 <= n1; n += 8) {
            #pragma unroll
            for (int j = 0; j < 8; j++) {
                float4 v = xp[(size_t)(n + j) * (DD / 4) + t];
                acc.x += v.x; acc.y += v.y; acc.z += v.z; acc.w += v.w;
            }
        }
        for (; n < n1; n++) {
            float4 v = xp[(size_t)n * (DD / 4) + t];
            acc.x += v.x; acc.y += v.y; acc.z += v.z; acc.w += v.w;
        }
        const float invN = 1.0f / (float)NN;
        float* dst = g_xbar + myb * DD + t * 4;
        atomicAdd(dst + 0, acc.x * invN);
        atomicAdd(dst + 1, acc.y * invN);
        atomicAdd(dst + 2, acc.z * invN);
        atomicAdd(dst + 3, acc.w * invN);
    }
    gridbar(GRID);

    // ===== Phase B: kbar chunk (smem) + upart (R6 verbatim) ===============
    if (blk < NCHU) {
        const int hbase = blk * HPERU;
        if (warp < HPERU) {
            const int h = hbase + warp;
            const float4* wk = (const float4*)(Wk + (size_t)h * DD);
            float4 wreg[8];
            #pragma unroll
            for (int i = 0; i < 8; i++) wreg[i] = wk[i * 32 + lane];

            float acc[BB];
            #pragma unroll
            for (int b = 0; b < BB; b++) {
                const float4* xb = (const float4*)(g_xbar + b * DD);
                float s = 0.f;
                #pragma unroll
                for (int i = 0; i < 8; i++) {
                    float4 xv = xb[i * 32 + lane];
                    s += wreg[i].x * xv.x + wreg[i].y * xv.y
                       + wreg[i].z * xv.z + wreg[i].w * xv.w;
                }
                acc[b] = s;
            }
            #pragma unroll
            for (int b = 0; b < BB; b++)
                #pragma unroll
                for (int o = 16; o > 0; o >>= 1)
                    acc[b] += __shfl_xor_sync(0xffffffffu, acc[b], o);

            if (lane < BB) {
                const float kb = acc[lane] + bk[h];  // lane b = kbar[b][h]
                s_kb[warp][lane] = kb;
                atomicAdd(&g_c[lane], bq[h] * kb);
            }
        }
        __syncthreads();

        float4 acc[BB];
        #pragma unroll
        for (int b = 0; b < BB; b++) acc[b] = make_float4(0.f, 0.f, 0.f, 0.f);
        #pragma unroll
        for (int hh = 0; hh < HPERU; hh++) {
            const float4 w = ((const float4*)(Wq + (size_t)(hbase + hh) * DD))[t];
            #pragma unroll
            for (int b = 0; b < BB; b++) {
                const float kb = s_kb[hh][b];
                acc[b].x = fmaf(w.x, kb, acc[b].x);
                acc[b].y = fmaf(w.y, kb, acc[b].y);
                acc[b].z = fmaf(w.z, kb, acc[b].z);
                acc[b].w = fmaf(w.w, kb, acc[b].w);
            }
        }
        float4* dst = (float4*)(g_upart[blk]);
        #pragma unroll
        for (int b = 0; b < BB; b++) dst[b * (DD / 4) + t] = acc[b];
    }
    gridbar(2u * GRID);

    // ===== Phase C: u = sum_c upart[c]  (L2-hot, R6 verbatim) =============
    if (blk < NCHU) {                       // 256 blocks: 8 strips x 32 groups
        const int ib = blk & 7;
        const int cbase = (blk >> 3) * CGRP;
        const int f4 = ib * 256 + t;
        float4 s = make_float4(0.f, 0.f, 0.f, 0.f);
        #pragma unroll
        for (int j = 0; j < CGRP; j++) {
            float4 v = ((const float4*)(g_upart[cbase + j]))[f4];
            s.x += v.x; s.y += v.y; s.z += v.z; s.w += v.w;
        }
        float* dst = g_u + f4 * 4;
        atomicAdd(dst + 0, s.x);
        atomicAdd(dst + 1, s.y);
        atomicAdd(dst + 2, s.z);
        atomicAdd(dst + 3, s.w);
    }
    gridbar(3u * GRID);

    // ===== Phase D: score own rows; first NSAVE come from smem ============
    {
        const float scale = rsqrtf((float)HH);
        const float cb = g_c[myb];
        const float4* up = (const float4*)(g_u + myb * DD);
        const float* xbase = x + (size_t)myb * NN * DD;
        float* obase = out + myb * NN;
        const int cnt = n1 - n0;

        for (int j = warp; j < cnt; j += 8) {
            const int n = n0 + j;
            float4 v[8];
            if (j < NSAVE) {
                const float4* xs = s_x + j * (DD / 4);
                #pragma unroll
                for (int i = 0; i < 8; i++) v[i] = xs[i * 32 + lane];
            } else {
                const float4* xp = (const float4*)(xbase + (size_t)n * DD);
                #pragma unroll
                for (int i = 0; i < 8; i++) v[i] = xp[i * 32 + lane];
            }
            float acc = 0.f;
            #pragma unroll
            for (int i = 0; i < 8; i++) {
                const float4 uv = up[i * 32 + lane];
                acc += v[i].x * uv.x + v[i].y * uv.y
                     + v[i].z * uv.z + v[i].w * uv.w;
            }
            #pragma unroll
            for (int o = 16; o > 0; o >>= 1)
                acc += __shfl_down_sync(0xffffffffu, acc, o);
            if (lane == 0) obase[n] = scale * (acc + cb);
        }
    }
}

// ---------------------------------------------------------------------------
extern "C" void kernel_launch(void* const* d_in, const int* in_sizes, int n_in,
                              void* d_out, int out_size) {
    const float* x  = (const float*)d_in[0];   // [B, N, D] f32
    const float* Wq = (const float*)d_in[1];   // [H, D]    f32
    const float* bq = (const float*)d_in[2];   // [H]       f32
    const float* Wk = (const float*)d_in[3];   // [H, D]    f32
    const float* bk = (const float*)d_in[4];   // [H]       f32
    float* out = (float*)d_out;                // [B, N]    f32

    cudaFuncSetAttribute(k_main, cudaFuncAttributeMaxDynamicSharedMemorySize,
                         SMEM_DYN);
    k_zero<<<(BB * DD + TPB - 1) / TPB, TPB>>>();
    k_main<<<GRID, TPB, SMEM_DYN>>>(x, Wq, bq, Wk, bk, out);
}

// round 13
// speedup vs baseline: 1.2215x; 1.2215x over previous
#include <cuda_runtime.h>
#include <math.h>

#define BB 8
#define NN 4096
#define DD 1024
#define HH 1792

#define GRID 296          // 148 SMs x 2 CTAs (forced by launch_bounds)
#define TPB 256
#define NCHU 256          // h-chunks in phase B
#define HPERU 7           // 256 * 7 = 1792
#define CGRP 8            // partials per phase-C block
#define BLKS_PER_B 37     // 296 / 8 blocks per batch in phase A

// Scratch (allocation-free contract): __device__ globals.
__device__ float g_xbar[BB * DD];          // mean_n x  (atomic-accumulated)
__device__ float g_upart[NCHU][BB * DD];   // partial Wq^T @ kbar
__device__ float g_u[BB * DD];             // reduced u (atomic-accumulated)
__device__ float g_c[BB];                  // bq . kbar (atomic-accumulated)
__device__ int   g_flag[NCHU];             // per-chunk upart-ready flags
__device__ unsigned g_bar;                 // grid barrier counter

// ---------------------------------------------------------------------------
// K0: reset accumulators + flags + barrier counter.
__global__ void k_zero() {
    int i = blockIdx.x * blockDim.x + threadIdx.x;
    if (i < BB * DD) { g_xbar[i] = 0.f; g_u[i] = 0.f; }
    if (i < NCHU) g_flag[i] = 0;
    if (i < BB) g_c[i] = 0.f;
    if (i == 0) g_bar = 0u;
}

// ---------------------------------------------------------------------------
// Software grid barrier. Safe: all GRID blocks co-resident
// (launch_bounds(256,2) on 148 SMs).
__device__ __forceinline__ void gridbar(unsigned target) {
    __syncthreads();
    if (threadIdx.x == 0) {
        __threadfence();
        atomicAdd(&g_bar, 1u);
        unsigned v;
        do {
            asm volatile("ld.volatile.global.u32 %0, [%1];"
                         : "=r"(v) : "l"(&g_bar));
            if (v < target) __nanosleep(64);
        } while (v < target);
        __threadfence();
    }
    __syncthreads();
}

// ---------------------------------------------------------------------------
__global__ void __launch_bounds__(TPB, 2)
k_main(const float* __restrict__ x,  const float* __restrict__ Wq,
       const float* __restrict__ bq, const float* __restrict__ Wk,
       const float* __restrict__ bk, float* __restrict__ out) {
    const int t = threadIdx.x;
    const int blk = blockIdx.x;
    const int warp = t >> 5, lane = t & 31;
    __shared__ float s_kb[HPERU][BB];

    // ===== Phase A: xbar[b,d] = (1/N) sum_n x[b,n,d]  (R6 verbatim) ======
    {
        const int b = blk / BLKS_PER_B;            // 0..7
        const int c = blk % BLKS_PER_B;
        const int n0 = (c * NN) / BLKS_PER_B;
        const int n1 = ((c + 1) * NN) / BLKS_PER_B;
        const float4* xp = (const float4*)(x + (size_t)b * NN * DD);

        float4 acc = make_float4(0.f, 0.f, 0.f, 0.f);
        int n = n0;
        for (; n + 8 <= n1; n += 8) {
            #pragma unroll
            for (int j = 0; j < 8; j++) {
                float4 v = xp[(size_t)(n + j) * (DD / 4) + t];
                acc.x += v.x; acc.y += v.y; acc.z += v.z; acc.w += v.w;
            }
        }
        for (; n < n1; n++) {
            float4 v = xp[(size_t)n * (DD / 4) + t];
            acc.x += v.x; acc.y += v.y; acc.z += v.z; acc.w += v.w;
        }
        const float invN = 1.0f / (float)NN;
        float* dst = g_xbar + b * DD + t * 4;
        atomicAdd(dst + 0, acc.x * invN);
        atomicAdd(dst + 1, acc.y * invN);
        atomicAdd(dst + 2, acc.z * invN);
        atomicAdd(dst + 3, acc.w * invN);
    }
    gridbar(GRID);

    // ===== Phase B: kbar chunk (smem) + upart; release per-chunk flag =====
    if (blk < NCHU) {
        const int hbase = blk * HPERU;
        if (warp < HPERU) {
            const int h = hbase + warp;
            const float4* wk = (const float4*)(Wk + (size_t)h * DD);
            float4 wreg[8];
            #pragma unroll
            for (int i = 0; i < 8; i++) wreg[i] = wk[i * 32 + lane];

            float acc[BB];
            #pragma unroll
            for (int b = 0; b < BB; b++) {
                const float4* xb = (const float4*)(g_xbar + b * DD);
                float s = 0.f;
                #pragma unroll
                for (int i = 0; i < 8; i++) {
                    float4 xv = xb[i * 32 + lane];
                    s += wreg[i].x * xv.x + wreg[i].y * xv.y
                       + wreg[i].z * xv.z + wreg[i].w * xv.w;
                }
                acc[b] = s;
            }
            #pragma unroll
            for (int b = 0; b < BB; b++)
                #pragma unroll
                for (int o = 16; o > 0; o >>= 1)
                    acc[b] += __shfl_xor_sync(0xffffffffu, acc[b], o);

            if (lane < BB) {
                const float kb = acc[lane] + bk[h];  // lane b = kbar[b][h]
                s_kb[warp][lane] = kb;
                atomicAdd(&g_c[lane], bq[h] * kb);
            }
        }
        __syncthreads();

        // Preload all 7 Wq rows (MLP=7), then pure-FMA accumulation.
        float4 wq[HPERU];
        #pragma unroll
        for (int hh = 0; hh < HPERU; hh++)
            wq[hh] = ((const float4*)(Wq + (size_t)(hbase + hh) * DD))[t];

        float4 acc[BB];
        #pragma unroll
        for (int b = 0; b < BB; b++) acc[b] = make_float4(0.f, 0.f, 0.f, 0.f);
        #pragma unroll
        for (int hh = 0; hh < HPERU; hh++) {
            #pragma unroll
            for (int b = 0; b < BB; b++) {
                const float kb = s_kb[hh][b];
                acc[b].x = fmaf(wq[hh].x, kb, acc[b].x);
                acc[b].y = fmaf(wq[hh].y, kb, acc[b].y);
                acc[b].z = fmaf(wq[hh].z, kb, acc[b].z);
                acc[b].w = fmaf(wq[hh].w, kb, acc[b].w);
            }
        }
        float4* dst = (float4*)(g_upart[blk]);
        #pragma unroll
        for (int b = 0; b < BB; b++) dst[b * (DD / 4) + t] = acc[b];

        // Release: stores visible, then flag.
        __threadfence();
        __syncthreads();
        if (t == 0) atomicExch(&g_flag[blk], 1);
    }

    // ===== Phase C: u = sum of my 8 producers' upart (flag-synced) ========
    if (blk < NCHU) {                       // 256 blocks: 8 strips x 32 groups
        const int ib = blk & 7;
        const int cbase = (blk >> 3) * CGRP;

        if (t < CGRP) {                     // wait for my 8 producers
            volatile int* f = g_flag + cbase + t;
            while (*f == 0) __nanosleep(64);
        }
        __syncthreads();
        __threadfence();                    // acquire producers' stores

        const int f4 = ib * 256 + t;
        float4 s = make_float4(0.f, 0.f, 0.f, 0.f);
        #pragma unroll
        for (int j = 0; j < CGRP; j++) {
            float4 v = ((const float4*)(g_upart[cbase + j]))[f4];
            s.x += v.x; s.y += v.y; s.z += v.z; s.w += v.w;
        }
        float* dst = g_u + f4 * 4;
        atomicAdd(dst + 0, s.x);
        atomicAdd(dst + 1, s.y);
        atomicAdd(dst + 2, s.z);
        atomicAdd(dst + 3, s.w);
    }
    gridbar(2u * GRID);

    // ===== Phase D: scores[r] = scale * (x[r].u[b] + c[b])  (R6 verbatim) =
    {
        const float scale = rsqrtf((float)HH);
        const int wglobal = blk * 8 + warp;          // 0..2367
        for (int r = wglobal; r < BB * NN; r += GRID * 8) {
            const int b = r >> 12;                   // N = 4096
            const float4* xp = (const float4*)(x + (size_t)r * DD);
            const float4* up = (const float4*)(g_u + b * DD);
            float acc = 0.f;
            #pragma unroll
            for (int i = 0; i < 8; i++) {
                float4 xv = xp[i * 32 + lane];
                float4 uv = up[i * 32 + lane];
                acc += xv.x * uv.x + xv.y * uv.y + xv.z * uv.z + xv.w * uv.w;
            }
            #pragma unroll
            for (int o = 16; o > 0; o >>= 1)
                acc += __shfl_down_sync(0xffffffffu, acc, o);
            if (lane == 0) out[r] = scale * (acc + g_c[b]);
        }
    }
}

// ---------------------------------------------------------------------------
extern "C" void kernel_launch(void* const* d_in, const int* in_sizes, int n_in,
                              void* d_out, int out_size) {
    const float* x  = (const float*)d_in[0];   // [B, N, D] f32
    const float* Wq = (const float*)d_in[1];   // [H, D]    f32
    const float* bq = (const float*)d_in[2];   // [H]       f32
    const float* Wk = (const float*)d_in[3];   // [H, D]    f32
    const float* bk = (const float*)d_in[4];   // [H]       f32
    float* out = (float*)d_out;                // [B, N]    f32

    k_zero<<<(BB * DD + TPB - 1) / TPB, TPB>>>();
    k_main<<<GRID, TPB>>>(x, Wq, bq, Wk, bk, out);
}